// round 3
// baseline (speedup 1.0000x reference)
#include <cuda_runtime.h>

#define T_TOK   4096
#define DMODEL  2048
#define NEXP    32
#define NTOPK   4
#define INTERN  1024
#define NPAIR   (T_TOK * NTOPK)

// ---------------- device scratch (no runtime allocation allowed) ----------------
__device__ int   g_cnt[NEXP];
__device__ int   g_tok[NEXP * T_TOK];
__device__ int   g_pair[NEXP * T_TOK];
__device__ float g_wt[NPAIR];
__device__ float g_h [(size_t)NPAIR * INTERN];      // routed up-proj output (per pair)
__device__ float g_y [(size_t)NPAIR * DMODEL];      // routed down-proj output (per pair, pre-scaled)
__device__ float g_hs[(size_t)T_TOK * 2 * INTERN];  // shared up-proj output

// ---------------- helpers ----------------
__device__ __forceinline__ unsigned f2tf(float x) {
    unsigned u;
    asm("cvt.rna.tf32.f32 %0, %1;" : "=r"(u) : "f"(x));
    return u;
}

__device__ __forceinline__ void mma8(float* d, const unsigned* a, const unsigned* b) {
    asm volatile(
        "mma.sync.aligned.m16n8k8.row.col.f32.tf32.tf32.f32 "
        "{%0,%1,%2,%3},{%4,%5,%6,%7},{%8,%9},{%0,%1,%2,%3};\n"
        : "+f"(d[0]), "+f"(d[1]), "+f"(d[2]), "+f"(d[3])
        : "r"(a[0]), "r"(a[1]), "r"(a[2]), "r"(a[3]), "r"(b[0]), "r"(b[1]));
}

// ---------------- kernel 0: zero expert counters ----------------
__global__ void zero_kernel() {
    if (threadIdx.x < NEXP) g_cnt[threadIdx.x] = 0;
}

// ---------------- kernel 1: gate (softmax + top-4 + routing lists) ----------------
__global__ void __launch_bounds__(128) gate_kernel(const float* __restrict__ X,
                                                   const float* __restrict__ GW) {
    __shared__ float xs[DMODEL];
    __shared__ float logits[NEXP];
    const int t = blockIdx.x, tid = threadIdx.x;

    const float4* xr = reinterpret_cast<const float4*>(X + (size_t)t * DMODEL);
#pragma unroll
    for (int it = 0; it < 4; it++)
        reinterpret_cast<float4*>(xs)[tid + 128 * it] = xr[tid + 128 * it];
    __syncthreads();

    // 4 threads per expert, each sums 512 elements
    const int e = tid >> 2, p = tid & 3;
    const float4* gw4 = reinterpret_cast<const float4*>(GW + (size_t)e * DMODEL + p * 512);
    const float4* xp4 = reinterpret_cast<const float4*>(xs + p * 512);
    float s = 0.f;
#pragma unroll 4
    for (int d = 0; d < 128; d++) {
        float4 a = xp4[d], b = gw4[d];
        s += a.x * b.x + a.y * b.y + a.z * b.z + a.w * b.w;
    }
    s += __shfl_down_sync(0xffffffffu, s, 2, 4);
    s += __shfl_down_sync(0xffffffffu, s, 1, 4);
    if (p == 0) logits[e] = s;
    __syncthreads();

    if (tid < 32) {  // warp 0 does softmax + top-4
        float v = logits[tid];
        float m = v;
#pragma unroll
        for (int o = 16; o; o >>= 1) m = fmaxf(m, __shfl_xor_sync(0xffffffffu, m, o));
        float ex  = __expf(v - m);
        float sum = ex;
#pragma unroll
        for (int o = 16; o; o >>= 1) sum += __shfl_xor_sync(0xffffffffu, sum, o);
        float val = ex / sum;  // softmax prob; ROUTE_SCALE = 1.0

#pragma unroll
        for (int k = 0; k < NTOPK; k++) {
            float bv = val;
            int   bi = tid;
#pragma unroll
            for (int o = 16; o; o >>= 1) {  // argmax, ties -> lower index (matches jax top_k)
                float ov = __shfl_xor_sync(0xffffffffu, bv, o);
                int   oi = __shfl_xor_sync(0xffffffffu, bi, o);
                if (ov > bv || (ov == bv && oi < bi)) { bv = ov; bi = oi; }
            }
            if (tid == 0) {
                int pr = t * NTOPK + k;
                g_wt[pr] = bv;
                int slot = atomicAdd(&g_cnt[bi], 1);
                g_tok[bi * T_TOK + slot]  = t;
                g_pair[bi * T_TOK + slot] = pr;
            }
            if (tid == bi) val = -1e30f;
        }
    }
}

// ---------------- fused up-projection GEMM: H = silu(A@W1^T) * (A@W3^T) ----------------
// Tiles: BM=128, BN=64, BK=32; 256 threads (8 warps), warp tile 32x32, dual accumulators.
template <bool ROUTED, int KDIM, int NTOT>
__global__ void __launch_bounds__(256) up_kernel(const float* __restrict__ X,
                                                 const float* __restrict__ W1b,
                                                 const float* __restrict__ W3b) {
    __shared__ unsigned As[128][36];
    __shared__ unsigned B1s[64][36];
    __shared__ unsigned B3s[64][36];
    __shared__ int rmap[128];
    __shared__ int omap[128];

    const int e  = blockIdx.z;
    const int m0 = blockIdx.x * 128;
    const int n0 = blockIdx.y * 64;
    int cnt;
    const float *B1, *B3;
    float* H;
    if constexpr (ROUTED) {
        cnt = g_cnt[e];
        if (m0 >= cnt) return;
        const size_t eo = (size_t)e * NTOT * KDIM;
        B1 = W1b + eo;
        B3 = W3b + eo;
        H  = g_h;
    } else {
        cnt = T_TOK;
        B1 = W1b;
        B3 = W3b;
        H  = g_hs;
    }
    const int tid = threadIdx.x;
    if (tid < 128) {
        int i  = m0 + tid;
        int ic = i < cnt ? i : cnt - 1;  // clamp padding rows (results never written)
        if constexpr (ROUTED) {
            rmap[tid] = g_tok[e * T_TOK + ic];
            omap[tid] = g_pair[e * T_TOK + ic];
        } else {
            rmap[tid] = ic;
            omap[tid] = ic;
        }
    }
    __syncthreads();

    const int lane = tid & 31, wrp = tid >> 5;
    const int wm = wrp & 3, wn = wrp >> 2;

    float acc1[2][4][4], acc3[2][4][4];
#pragma unroll
    for (int i = 0; i < 2; i++)
#pragma unroll
        for (int j = 0; j < 4; j++)
#pragma unroll
            for (int r = 0; r < 4; r++) { acc1[i][j][r] = 0.f; acc3[i][j][r] = 0.f; }

    float4 pa[4], pb1[2], pb3[2];

    auto GLOAD = [&](int kt) {
        const int k0 = kt * 32;
#pragma unroll
        for (int it = 0; it < 4; it++) {
            int f = tid + 256 * it, r = f >> 3, c = (f & 7) << 2;
            pa[it] = *reinterpret_cast<const float4*>(X + (size_t)rmap[r] * KDIM + k0 + c);
        }
#pragma unroll
        for (int it = 0; it < 2; it++) {
            int f = tid + 256 * it, r = f >> 3, c = (f & 7) << 2;
            size_t off = (size_t)(n0 + r) * KDIM + k0 + c;
            pb1[it] = *reinterpret_cast<const float4*>(B1 + off);
            pb3[it] = *reinterpret_cast<const float4*>(B3 + off);
        }
    };
    auto SSTORE = [&]() {
#pragma unroll
        for (int it = 0; it < 4; it++) {
            int f = tid + 256 * it, r = f >> 3, c = (f & 7) << 2;
            uint4 v = { f2tf(pa[it].x), f2tf(pa[it].y), f2tf(pa[it].z), f2tf(pa[it].w) };
            *reinterpret_cast<uint4*>(&As[r][c]) = v;
        }
#pragma unroll
        for (int it = 0; it < 2; it++) {
            int f = tid + 256 * it, r = f >> 3, c = (f & 7) << 2;
            uint4 v1 = { f2tf(pb1[it].x), f2tf(pb1[it].y), f2tf(pb1[it].z), f2tf(pb1[it].w) };
            *reinterpret_cast<uint4*>(&B1s[r][c]) = v1;
            uint4 v3 = { f2tf(pb3[it].x), f2tf(pb3[it].y), f2tf(pb3[it].z), f2tf(pb3[it].w) };
            *reinterpret_cast<uint4*>(&B3s[r][c]) = v3;
        }
    };

    GLOAD(0);
    const int KIT = KDIM / 32;
    for (int kt = 0; kt < KIT; kt++) {
        if (kt) __syncthreads();
        SSTORE();
        __syncthreads();
        if (kt + 1 < KIT) GLOAD(kt + 1);
#pragma unroll
        for (int kk = 0; kk < 4; kk++) {
            const int c = kk * 8 + (lane & 3);
            unsigned a[2][4];
#pragma unroll
            for (int i = 0; i < 2; i++) {
                const int r = wm * 32 + i * 16 + (lane >> 2);
                a[i][0] = As[r][c];
                a[i][1] = As[r + 8][c];
                a[i][2] = As[r][c + 4];
                a[i][3] = As[r + 8][c + 4];
            }
#pragma unroll
            for (int j = 0; j < 4; j++) {
                const int n = wn * 32 + j * 8 + (lane >> 2);
                unsigned b1[2] = { B1s[n][c], B1s[n][c + 4] };
                unsigned b3[2] = { B3s[n][c], B3s[n][c + 4] };
#pragma unroll
                for (int i = 0; i < 2; i++) {
                    mma8(acc1[i][j], a[i], b1);
                    mma8(acc3[i][j], a[i], b3);
                }
            }
        }
    }

    // epilogue: h = silu(u1) * u3
#pragma unroll
    for (int i = 0; i < 2; i++)
#pragma unroll
        for (int r = 0; r < 4; r++) {
            const int lm = wm * 32 + i * 16 + ((r & 2) ? 8 : 0) + (lane >> 2);
            if (ROUTED && (m0 + lm) >= cnt) continue;
            const size_t orow = (size_t)omap[lm] * NTOT;
#pragma unroll
            for (int j = 0; j < 4; j++) {
                const int gc = n0 + wn * 32 + j * 8 + ((lane & 3) * 2) + (r & 1);
                float u1 = acc1[i][j][r], u3 = acc3[i][j][r];
                H[orow + gc] = (u1 / (1.f + __expf(-u1))) * u3;
            }
        }
}

// ---------------- down-projection GEMM: OUT = (A@W^T) * scale ----------------
template <bool ROUTED, int KDIM, int NTOT>
__global__ void __launch_bounds__(256) down_kernel(const float* __restrict__ Wb,
                                                   float* __restrict__ OUTp) {
    __shared__ unsigned As[128][36];
    __shared__ unsigned Bs[64][36];
    __shared__ int   rmap[128];
    __shared__ int   omap[128];
    __shared__ float smw[128];

    const int e  = blockIdx.z;
    const int m0 = blockIdx.x * 128;
    const int n0 = blockIdx.y * 64;
    int cnt;
    const float *B, *A;
    float* OUT;
    if constexpr (ROUTED) {
        cnt = g_cnt[e];
        if (m0 >= cnt) return;
        B   = Wb + (size_t)e * NTOT * KDIM;
        A   = g_h;
        OUT = g_y;
    } else {
        cnt = T_TOK;
        B   = Wb;
        A   = g_hs;
        OUT = OUTp;
    }
    const int tid = threadIdx.x;
    if (tid < 128) {
        int i  = m0 + tid;
        int ic = i < cnt ? i : cnt - 1;
        if constexpr (ROUTED) {
            int pr = g_pair[e * T_TOK + ic];
            rmap[tid] = pr;
            omap[tid] = pr;
            smw[tid]  = g_wt[pr];
        } else {
            rmap[tid] = ic;
            omap[tid] = ic;
            smw[tid]  = 1.f;
        }
    }
    __syncthreads();

    const int lane = tid & 31, wrp = tid >> 5;
    const int wm = wrp & 3, wn = wrp >> 2;

    float acc[2][4][4];
#pragma unroll
    for (int i = 0; i < 2; i++)
#pragma unroll
        for (int j = 0; j < 4; j++)
#pragma unroll
            for (int r = 0; r < 4; r++) acc[i][j][r] = 0.f;

    float4 pa[4], pb[2];

    auto GLOAD = [&](int kt) {
        const int k0 = kt * 32;
#pragma unroll
        for (int it = 0; it < 4; it++) {
            int f = tid + 256 * it, r = f >> 3, c = (f & 7) << 2;
            pa[it] = *reinterpret_cast<const float4*>(A + (size_t)rmap[r] * KDIM + k0 + c);
        }
#pragma unroll
        for (int it = 0; it < 2; it++) {
            int f = tid + 256 * it, r = f >> 3, c = (f & 7) << 2;
            pb[it] = *reinterpret_cast<const float4*>(B + (size_t)(n0 + r) * KDIM + k0 + c);
        }
    };
    auto SSTORE = [&]() {
#pragma unroll
        for (int it = 0; it < 4; it++) {
            int f = tid + 256 * it, r = f >> 3, c = (f & 7) << 2;
            uint4 v = { f2tf(pa[it].x), f2tf(pa[it].y), f2tf(pa[it].z), f2tf(pa[it].w) };
            *reinterpret_cast<uint4*>(&As[r][c]) = v;
        }
#pragma unroll
        for (int it = 0; it < 2; it++) {
            int f = tid + 256 * it, r = f >> 3, c = (f & 7) << 2;
            uint4 v = { f2tf(pb[it].x), f2tf(pb[it].y), f2tf(pb[it].z), f2tf(pb[it].w) };
            *reinterpret_cast<uint4*>(&Bs[r][c]) = v;
        }
    };

    GLOAD(0);
    const int KIT = KDIM / 32;
    for (int kt = 0; kt < KIT; kt++) {
        if (kt) __syncthreads();
        SSTORE();
        __syncthreads();
        if (kt + 1 < KIT) GLOAD(kt + 1);
#pragma unroll
        for (int kk = 0; kk < 4; kk++) {
            const int c = kk * 8 + (lane & 3);
            unsigned a[2][4];
#pragma unroll
            for (int i = 0; i < 2; i++) {
                const int r = wm * 32 + i * 16 + (lane >> 2);
                a[i][0] = As[r][c];
                a[i][1] = As[r + 8][c];
                a[i][2] = As[r][c + 4];
                a[i][3] = As[r + 8][c + 4];
            }
#pragma unroll
            for (int j = 0; j < 4; j++) {
                const int n = wn * 32 + j * 8 + (lane >> 2);
                unsigned b[2] = { Bs[n][c], Bs[n][c + 4] };
#pragma unroll
                for (int i = 0; i < 2; i++) mma8(acc[i][j], a[i], b);
            }
        }
    }

#pragma unroll
    for (int i = 0; i < 2; i++)
#pragma unroll
        for (int r = 0; r < 4; r++) {
            const int lm = wm * 32 + i * 16 + ((r & 2) ? 8 : 0) + (lane >> 2);
            if (ROUTED && (m0 + lm) >= cnt) continue;
            const size_t orow = (size_t)omap[lm] * NTOT;
            const float  w    = smw[lm];
#pragma unroll
            for (int j = 0; j < 4; j++) {
                const int gc = n0 + wn * 32 + j * 8 + ((lane & 3) * 2) + (r & 1);
                OUT[orow + gc] = acc[i][j][r] * w;
            }
        }
}

// ---------------- combine: out = z (already in out) + sum_k y_pair ----------------
__global__ void combine_kernel(float* __restrict__ out) {
    const int total = T_TOK * DMODEL / 4;
    int idx = blockIdx.x * blockDim.x + threadIdx.x;
    if (idx >= total) return;
    int t = idx / (DMODEL / 4);
    int c = idx - t * (DMODEL / 4);
    float4 z = reinterpret_cast<float4*>(out)[idx];
#pragma unroll
    for (int k = 0; k < NTOPK; k++) {
        float4 v = reinterpret_cast<const float4*>(g_y)[(size_t)(t * NTOPK + k) * (DMODEL / 4) + c];
        z.x += v.x; z.y += v.y; z.z += v.z; z.w += v.w;
    }
    reinterpret_cast<float4*>(out)[idx] = z;
}

// ---------------- launch ----------------
extern "C" void kernel_launch(void* const* d_in, const int* in_sizes, int n_in,
                              void* d_out, int out_size) {
    const float* x   = (const float*)d_in[0];
    const float* gw  = (const float*)d_in[1];
    const float* w1  = (const float*)d_in[2];
    const float* w2  = (const float*)d_in[3];
    const float* w3  = (const float*)d_in[4];
    const float* sw1 = (const float*)d_in[5];
    const float* sw2 = (const float*)d_in[6];
    const float* sw3 = (const float*)d_in[7];
    float* out = (float*)d_out;

    zero_kernel<<<1, 32>>>();
    gate_kernel<<<T_TOK, 128>>>(x, gw);

    // routed experts: up (fused w1/w3 + silu), then down (scaled into per-pair y)
    up_kernel<true, DMODEL, INTERN><<<dim3(T_TOK / 128, INTERN / 64, NEXP), 256>>>(x, w1, w3);
    down_kernel<true, INTERN, DMODEL><<<dim3(T_TOK / 128, DMODEL / 64, NEXP), 256>>>(w2, nullptr);

    // shared expert: up, then down writes z directly into d_out
    up_kernel<false, DMODEL, 2 * INTERN><<<dim3(T_TOK / 128, (2 * INTERN) / 64, 1), 256>>>(x, sw1, sw3);
    down_kernel<false, 2 * INTERN, DMODEL><<<dim3(T_TOK / 128, DMODEL / 64, 1), 256>>>(sw2, out);

    // out += sum over the 4 routed contributions per token
    combine_kernel<<<(T_TOK * DMODEL / 4 + 255) / 256, 256>>>(out);
}

// round 10
// speedup vs baseline: 1.0019x; 1.0019x over previous
#include <cuda_runtime.h>
#include <cstdint>

#define T_TOK   4096
#define DMODEL  2048
#define NEXP    32
#define NTOPK   4
#define INTERN  1024
#define NPAIR   (T_TOK * NTOPK)

// ---------------- device scratch (no runtime allocation allowed) ----------------
__device__ int   g_cnt[NEXP];
__device__ int   g_tok[NEXP * T_TOK];
__device__ int   g_pair[NEXP * T_TOK];
__device__ float g_wt[NPAIR];
__device__ float g_h [(size_t)NPAIR * INTERN];      // routed up output (per pair)
__device__ float g_y [(size_t)NPAIR * DMODEL];      // routed down output (per pair, scaled)
__device__ float g_hs[(size_t)T_TOK * 2 * INTERN];  // shared up output

// ---------------- helpers ----------------
__device__ __forceinline__ unsigned f2tf(float x) {
    unsigned u; asm("cvt.rna.tf32.f32 %0, %1;" : "=r"(u) : "f"(x)); return u;
}
__device__ __forceinline__ void mma8(float* d, const unsigned* a, const unsigned* b) {
    asm volatile(
        "mma.sync.aligned.m16n8k8.row.col.f32.tf32.tf32.f32 "
        "{%0,%1,%2,%3},{%4,%5,%6,%7},{%8,%9},{%0,%1,%2,%3};\n"
        : "+f"(d[0]), "+f"(d[1]), "+f"(d[2]), "+f"(d[3])
        : "r"(a[0]), "r"(a[1]), "r"(a[2]), "r"(a[3]), "r"(b[0]), "r"(b[1]));
}

// ---------------- kernel 0: zero expert counters ----------------
__global__ void zero_kernel() {
    if (threadIdx.x < NEXP) g_cnt[threadIdx.x] = 0;
}

// ---------------- kernel 1: gate, 4 tokens per block ----------------
__global__ void __launch_bounds__(128) gate_kernel(const float* __restrict__ X,
                                                   const float* __restrict__ GW) {
    __shared__ float xs[4 * DMODEL];
    __shared__ float logits[4][NEXP];
    const int t0 = blockIdx.x * 4, tid = threadIdx.x;

    const float4* xr = reinterpret_cast<const float4*>(X + (size_t)t0 * DMODEL);
#pragma unroll
    for (int i = 0; i < 16; i++)
        reinterpret_cast<float4*>(xs)[tid + 128 * i] = xr[tid + 128 * i];
    __syncthreads();

    const int e = tid >> 2, p = tid & 3;
    const float4* gw4 = reinterpret_cast<const float4*>(GW + (size_t)e * DMODEL + p * 512);
    const float4* x0 = reinterpret_cast<const float4*>(xs + 0 * DMODEL + p * 512);
    const float4* x1 = reinterpret_cast<const float4*>(xs + 1 * DMODEL + p * 512);
    const float4* x2 = reinterpret_cast<const float4*>(xs + 2 * DMODEL + p * 512);
    const float4* x3 = reinterpret_cast<const float4*>(xs + 3 * DMODEL + p * 512);
    float a0 = 0.f, a1 = 0.f, a2 = 0.f, a3 = 0.f;
#pragma unroll 4
    for (int d = 0; d < 128; d++) {
        const float4 b = gw4[d];
        float4 a;
        a = x0[d]; a0 += a.x * b.x + a.y * b.y + a.z * b.z + a.w * b.w;
        a = x1[d]; a1 += a.x * b.x + a.y * b.y + a.z * b.z + a.w * b.w;
        a = x2[d]; a2 += a.x * b.x + a.y * b.y + a.z * b.z + a.w * b.w;
        a = x3[d]; a3 += a.x * b.x + a.y * b.y + a.z * b.z + a.w * b.w;
    }
#pragma unroll
    for (int o = 2; o; o >>= 1) {
        a0 += __shfl_down_sync(0xffffffffu, a0, o, 4);
        a1 += __shfl_down_sync(0xffffffffu, a1, o, 4);
        a2 += __shfl_down_sync(0xffffffffu, a2, o, 4);
        a3 += __shfl_down_sync(0xffffffffu, a3, o, 4);
    }
    if (p == 0) { logits[0][e] = a0; logits[1][e] = a1; logits[2][e] = a2; logits[3][e] = a3; }
    __syncthreads();

    if (tid < 32) {
        for (int t = 0; t < 4; t++) {
            float v = logits[t][tid];
            float m = v;
#pragma unroll
            for (int o = 16; o; o >>= 1) m = fmaxf(m, __shfl_xor_sync(0xffffffffu, m, o));
            float ex = __expf(v - m), sum = ex;
#pragma unroll
            for (int o = 16; o; o >>= 1) sum += __shfl_xor_sync(0xffffffffu, sum, o);
            float val = ex / sum;
#pragma unroll
            for (int k = 0; k < NTOPK; k++) {
                float bv = val; int bi = tid;
#pragma unroll
                for (int o = 16; o; o >>= 1) {  // argmax, ties -> lower index
                    float ov = __shfl_xor_sync(0xffffffffu, bv, o);
                    int   oi = __shfl_xor_sync(0xffffffffu, bi, o);
                    if (ov > bv || (ov == bv && oi < bi)) { bv = ov; bi = oi; }
                }
                if (tid == 0) {
                    int pr = (t0 + t) * NTOPK + k;
                    g_wt[pr] = bv;
                    int slot = atomicAdd(&g_cnt[bi], 1);
                    g_tok[bi * T_TOK + slot]  = t0 + t;
                    g_pair[bi * T_TOK + slot] = pr;
                }
                if (tid == bi) val = -1e30f;
            }
        }
    }
}

// ================= unified tf32 mma.sync GEMM =================
// CTA tile: M=128, N=128, K-chunk=32. 8 warps as 2(m) x 4(n), warp tile 64x32.
// All SMEM is STATIC (33.5KB total) -> no dynamic-smem opt-in, capture-safe.
// Operands live in SMEM pre-converted to tf32 in mma *fragment layout*:
//   A: [mtile 8][slice 4][lane^slice][4 regs]  (16KB)
//   B: [ntile 16][spair 2][lane^spair][4 regs] (16KB), slots (b0,b1)@s=2sp,(b0,b1)@s=2sp+1
// so every mainloop operand fetch is one conflict-free ld.shared.v4.
//
// UP mode: B rows interleave W1/W3 (even n -> W1[n/2], odd -> W3[n/2]); the mma C
// fragment then holds (u1,u3) in adjacent regs -> silu fused in the epilogue,
// writing NTOT = N/2 features per tile. DOWN mode: plain GEMM * routing weight.
template <bool ROUTED, bool UP, int KDIM, int NTOT>
__global__ void __launch_bounds__(256) gemm_tc(const float* __restrict__ Xin,
                                               const float* __restrict__ Bw1,
                                               const float* __restrict__ Bw3,
                                               float* __restrict__ OUTp) {
    __shared__ unsigned Asm[4096];   // 16KB
    __shared__ unsigned Bsm[4096];   // 16KB
    __shared__ int   rmap[128], omap[128];
    __shared__ float smw[128];

    const int e  = blockIdx.z;
    const int m0 = blockIdx.x * 128;
    const int n0 = blockIdx.y * 128;
    int cnt;
    const float *Ap, *W1, *W3 = nullptr;
    float* OUT;
    if constexpr (ROUTED) {
        cnt = g_cnt[e];
        if (m0 >= cnt) return;
        if constexpr (UP) {
            const size_t eo = (size_t)e * INTERN * DMODEL;
            W1 = Bw1 + eo; W3 = Bw3 + eo; Ap = Xin; OUT = g_h;
        } else {
            W1 = Bw1 + (size_t)e * DMODEL * INTERN; Ap = g_h; OUT = g_y;
        }
    } else {
        cnt = T_TOK;
        if constexpr (UP) { W1 = Bw1; W3 = Bw3; Ap = Xin; OUT = g_hs; }
        else              { W1 = Bw1; Ap = g_hs; OUT = OUTp; }
    }

    const int tid = threadIdx.x;
    if (tid < 128) {
        int ic = m0 + tid; if (ic >= cnt) ic = cnt - 1;   // clamp; outputs suppressed
        if constexpr (ROUTED) {
            if constexpr (UP) { rmap[tid] = g_tok[e * T_TOK + ic]; omap[tid] = g_pair[e * T_TOK + ic]; }
            else {
                int pr = g_pair[e * T_TOK + ic];
                rmap[tid] = pr; omap[tid] = pr; smw[tid] = g_wt[pr];
            }
        } else { rmap[tid] = ic; omap[tid] = ic; if constexpr (!UP) smw[tid] = 1.f; }
    }
    __syncthreads();

    const int lane = tid & 31, wid = tid >> 5;
    const int wm = wid >> 2, wn = wid & 3;   // 2 x 4 warp grid, warp tile 64x32

    // staging geometry: 8 threads per row, each owns a float4 column chunk
    const int rbase = tid >> 3, cof = (tid & 7) * 4;
    const float* bsrc;
    if constexpr (UP) bsrc = (rbase & 1) ? W3 : W1;   // B-row parity fixed per thread
    else              bsrc = W1;

    float acc[4][4][4];
#pragma unroll
    for (int mt = 0; mt < 4; mt++)
#pragma unroll
        for (int nt = 0; nt < 4; nt++)
#pragma unroll
            for (int r = 0; r < 4; r++) acc[mt][nt][r] = 0.f;

    float4 pa[4], pb[4];
    auto GLOAD = [&](int kt) {
        const int k0 = kt * 32;
#pragma unroll
        for (int i = 0; i < 4; i++) {
            const int r = rbase + 32 * i;                       // A row in tile (0..127)
            pa[i] = *reinterpret_cast<const float4*>(Ap + (size_t)rmap[r] * KDIM + k0 + cof);
        }
#pragma unroll
        for (int i = 0; i < 4; i++) {
            const int n = rbase + 32 * i;                       // B row in tile (0..127)
            size_t row;
            if constexpr (UP) row = (size_t)((n0 + n) >> 1);
            else              row = (size_t)(n0 + n);
            pb[i] = *reinterpret_cast<const float4*>(bsrc + row * KDIM + k0 + cof);
        }
    };

    // scatter staging regs into fragment layout (tf32-converted)
    const int s_a   = cof >> 3;                 // k-slice of this thread's 4 floats
    const int half  = (cof >> 2) & 1;           // high half of the 8-k slice?
    const int spair = s_a >> 1;
    const int slot  = (s_a & 1) * 2 + half;
    auto SSTORE = [&]() {
#pragma unroll
        for (int i = 0; i < 4; i++) {
            const int r = rbase + 32 * i;
            const int mt = r >> 4, rr = r & 15;
            const int q  = (rr >> 3) + 2 * half;
            const int lp = (rr & 7) * 4;
            const unsigned base = (unsigned)(((mt * 4 + s_a) * 32) * 4 + q);
            const float v[4] = { pa[i].x, pa[i].y, pa[i].z, pa[i].w };
#pragma unroll
            for (int e2 = 0; e2 < 4; e2++)
                Asm[base + (((lp + e2) ^ s_a) << 2)] = f2tf(v[e2]);
        }
#pragma unroll
        for (int i = 0; i < 4; i++) {
            const int n  = rbase + 32 * i;
            const int nt = n >> 3;
            const int lp = (n & 7) * 4;
            const unsigned base = (unsigned)(((nt * 2 + spair) * 32) * 4 + slot);
            const float v[4] = { pb[i].x, pb[i].y, pb[i].z, pb[i].w };
#pragma unroll
            for (int e2 = 0; e2 < 4; e2++)
                Bsm[base + (((lp + e2) ^ spair) << 2)] = f2tf(v[e2]);
        }
    };

    GLOAD(0);
    const int KIT = KDIM / 32;
    for (int kt = 0; kt < KIT; kt++) {
        if (kt) __syncthreads();
        SSTORE();
        __syncthreads();
        if (kt + 1 < KIT) GLOAD(kt + 1);

#pragma unroll
        for (int sp = 0; sp < 2; sp++) {
            uint4 bf[4];
#pragma unroll
            for (int nt = 0; nt < 4; nt++) {
                const int gnt = wn * 4 + nt;
                bf[nt] = *reinterpret_cast<const uint4*>(
                    &Bsm[((gnt * 2 + sp) * 32 + (lane ^ sp)) * 4]);
            }
#pragma unroll
            for (int sh = 0; sh < 2; sh++) {
                const int s = sp * 2 + sh;
                uint4 af[4];
#pragma unroll
                for (int mt = 0; mt < 4; mt++) {
                    const int gmt = wm * 4 + mt;
                    af[mt] = *reinterpret_cast<const uint4*>(
                        &Asm[((gmt * 4 + s) * 32 + (lane ^ s)) * 4]);
                }
#pragma unroll
                for (int mt = 0; mt < 4; mt++)
#pragma unroll
                    for (int nt = 0; nt < 4; nt++) {
                        unsigned b2[2];
                        b2[0] = sh ? bf[nt].z : bf[nt].x;
                        b2[1] = sh ? bf[nt].w : bf[nt].y;
                        mma8(acc[mt][nt], reinterpret_cast<const unsigned*>(&af[mt]), b2);
                    }
            }
        }
    }

    // ---- epilogue ----
#pragma unroll
    for (int mt = 0; mt < 4; mt++) {
        const int lr0 = wm * 64 + mt * 16 + (lane >> 2);
#pragma unroll
        for (int h = 0; h < 2; h++) {
            const int lr = lr0 + 8 * h;
            if (ROUTED && (m0 + lr) >= cnt) continue;
            const size_t orow = (size_t)omap[lr] * NTOT;
            if constexpr (UP) {
#pragma unroll
                for (int nt = 0; nt < 4; nt++) {
                    const int f = ((n0 + (wn * 4 + nt) * 8) >> 1) + (lane & 3);
                    const float u1 = acc[mt][nt][h * 2], u3 = acc[mt][nt][h * 2 + 1];
                    OUT[orow + f] = u1 / (1.f + __expf(-u1)) * u3;
                }
            } else {
                const float w = smw[lr];
#pragma unroll
                for (int nt = 0; nt < 4; nt++) {
                    const int g = n0 + (wn * 4 + nt) * 8 + 2 * (lane & 3);
                    float2 v;
                    v.x = acc[mt][nt][h * 2] * w;
                    v.y = acc[mt][nt][h * 2 + 1] * w;
                    *reinterpret_cast<float2*>(OUT + orow + g) = v;
                }
            }
        }
    }
}

// ---------------- combine: out = z (already in out) + sum_k y_pair ----------------
__global__ void combine_kernel(float* __restrict__ out) {
    const int total = T_TOK * DMODEL / 4;
    int idx = blockIdx.x * blockDim.x + threadIdx.x;
    if (idx >= total) return;
    int t = idx / (DMODEL / 4);
    int c = idx - t * (DMODEL / 4);
    float4 z = reinterpret_cast<float4*>(out)[idx];
#pragma unroll
    for (int k = 0; k < NTOPK; k++) {
        float4 v = reinterpret_cast<const float4*>(g_y)[(size_t)(t * NTOPK + k) * (DMODEL / 4) + c];
        z.x += v.x; z.y += v.y; z.z += v.z; z.w += v.w;
    }
    reinterpret_cast<float4*>(out)[idx] = z;
}

// ---------------- launch ----------------
extern "C" void kernel_launch(void* const* d_in, const int* in_sizes, int n_in,
                              void* d_out, int out_size) {
    const float* x   = (const float*)d_in[0];
    const float* gw  = (const float*)d_in[1];
    const float* w1  = (const float*)d_in[2];
    const float* w2  = (const float*)d_in[3];
    const float* w3  = (const float*)d_in[4];
    const float* sw1 = (const float*)d_in[5];
    const float* sw2 = (const float*)d_in[6];
    const float* sw3 = (const float*)d_in[7];
    float* out = (float*)d_out;

    zero_kernel<<<1, 32>>>();
    gate_kernel<<<T_TOK / 4, 128>>>(x, gw);

    // routed: up (interleaved W1/W3 -> silu fused), then down (scaled into per-pair y)
    gemm_tc<true,  true,  DMODEL, INTERN><<<dim3(T_TOK / 128, (2 * INTERN) / 128, NEXP), 256>>>(x, w1, w3, nullptr);
    gemm_tc<true,  false, INTERN, DMODEL><<<dim3(T_TOK / 128, DMODEL / 128, NEXP), 256>>>(x, w2, nullptr, nullptr);

    // shared expert: up, then down writes z directly into d_out
    gemm_tc<false, true,  DMODEL, 2 * INTERN><<<dim3(T_TOK / 128, (4 * INTERN) / 128, 1), 256>>>(x, sw1, sw3, nullptr);
    gemm_tc<false, false, 2 * INTERN, DMODEL><<<dim3(T_TOK / 128, DMODEL / 128, 1), 256>>>(x, sw2, nullptr, out);

    combine_kernel<<<(T_TOK * DMODEL / 4 + 255) / 256, 256>>>(out);
}